// round 15
// baseline (speedup 1.0000x reference)
#include <cuda_runtime.h>

#define NN 256
#define BB 2
#define NNODE (BB*NN)

#define RSQRT3 0.5773502691896258f
#define INV_FAN 0.1767766952966369f   // 1/sqrt(32)

// partial G: per (node, half) -> [f*4+c], f in [0,33), f==32 = bias feature
__device__ float g_G2[2*NNODE][132];

#define PACK_F32X2(out, lo, hi) \
    asm("mov.b64 %0, {%1, %2};" : "=l"(out) : "f"(lo), "f"(hi))
#define UNPACK_F32X2(lo, hi, in) \
    asm("mov.b64 {%0, %1}, %2;" : "=f"(lo), "=f"(hi) : "l"(in))
#define FMA_F32X2(d, a, b, c) \
    asm("fma.rn.f32x2 %0, %1, %2, %3;" : "=l"(d) : "l"(a), "l"(b), "l"(c))
#define ADD_F32X2(d, a, b) \
    asm("add.rn.f32x2 %0, %1, %2;" : "=l"(d) : "l"(a), "l"(b))

#define CP_ASYNC16(dst_u32, src_ptr) \
    asm volatile("cp.async.ca.shared.global [%0], [%1], 16;" :: "r"(dst_u32), "l"(src_ptr))
#define CP_COMMIT() asm volatile("cp.async.commit_group;" ::: "memory")
#define CP_WAIT2()  asm volatile("cp.async.wait_group 2;" ::: "memory")
#define CP_WAIT1()  asm volatile("cp.async.wait_group 1;" ::: "memory")
#define CP_WAIT0()  asm volatile("cp.async.wait_group 0;" ::: "memory")

// ---------------------------------------------------------------------------
// Kernel A: edge reduction, block per (node, half), 128 rows.
// ea read DIRECTLY from gmem via broadcast LDG.128 (no smem round-trip,
// no cp.async, only one barrier). lane = f; warp owns 16 rows.
// ---------------------------------------------------------------------------
__global__ __launch_bounds__(256, 3) void edge_kernel(
    const float* __restrict__ edge_attr,
    const float* __restrict__ edge_sh,
    const float* __restrict__ mask,
    const float* __restrict__ fc_w1,
    const float* __restrict__ fc_b1)
{
    __shared__ __align__(16) float shp[128 * 4];   // premultiplied sh
    __shared__ __align__(16) float w1s[1024];      // [j][f]
    __shared__ float b1s[32];
    __shared__ float Gp[8][132];

    const int blk  = blockIdx.x;
    const int node = blk >> 1;
    const int half = blk & 1;
    const int b = node >> 8;
    const int n = node & 255;
    const int m0 = half * 128;
    const int t = threadIdx.x;
    const int lane = t & 31;
    const int wid = t >> 5;

    // prologue: W1, b1, premultiplied sh'
    ((float4*)w1s)[t] = ((const float4*)fc_w1)[t];
    if (t < 32) b1s[t] = fc_b1[t];
    if (t < 128) {
        int m = m0 + t;
        float mf = mask[b * NN + m] * (m != n ? 1.0f : 0.0f);
        float4 s = ((const float4*)(edge_sh + (size_t)node * NN * 4))[m];
        s.x *= mf; s.y *= mf; s.z *= mf; s.w *= mf;
        ((float4*)shp)[t] = s;
    }
    __syncthreads();

    unsigned long long w1p[16];
    #pragma unroll
    for (int j = 0; j < 16; j++)
        PACK_F32X2(w1p[j], w1s[(2*j) * 32 + lane], w1s[(2*j+1) * 32 + lane]);
    unsigned long long bias2;
    PACK_F32X2(bias2, b1s[lane], 0.0f);

    // ea rows for this block; row r = ea2 + r*8 (8 x 16B per row)
    const ulonglong2* ea2 =
        (const ulonglong2*)(edge_attr + (size_t)node * NN * 32 + (size_t)m0 * 32);

    unsigned long long acc01 = 0ULL, acc23 = 0ULL;
    const ulonglong2* sh2 = (const ulonglong2*)shp;

    // warp owns rows [wid*16, wid*16+16); 2 rows per iteration
    #pragma unroll
    for (int it = 0; it < 8; it++) {
        const int r0 = wid * 16 + it * 2;
        const ulonglong2* rA = ea2 + (size_t)r0 * 8;
        const ulonglong2* rB = rA + 8;

        unsigned long long cA0 = bias2, cA1 = 0ULL;
        unsigned long long cB0 = bias2, cB1 = 0ULL;

        ulonglong2 a0 = rA[0], a1 = rA[1], a2v = rA[2], a3 = rA[3];
        ulonglong2 b0 = rB[0], b1v = rB[1], b2 = rB[2], b3 = rB[3];
        FMA_F32X2(cA0, a0.x,  w1p[0], cA0);
        FMA_F32X2(cA1, a0.y,  w1p[1], cA1);
        FMA_F32X2(cB0, b0.x,  w1p[0], cB0);
        FMA_F32X2(cB1, b0.y,  w1p[1], cB1);
        FMA_F32X2(cA0, a1.x,  w1p[2], cA0);
        FMA_F32X2(cA1, a1.y,  w1p[3], cA1);
        FMA_F32X2(cB0, b1v.x, w1p[2], cB0);
        FMA_F32X2(cB1, b1v.y, w1p[3], cB1);
        FMA_F32X2(cA0, a2v.x, w1p[4], cA0);
        FMA_F32X2(cA1, a2v.y, w1p[5], cA1);
        FMA_F32X2(cB0, b2.x,  w1p[4], cB0);
        FMA_F32X2(cB1, b2.y,  w1p[5], cB1);
        FMA_F32X2(cA0, a3.x,  w1p[6], cA0);
        FMA_F32X2(cA1, a3.y,  w1p[7], cA1);
        FMA_F32X2(cB0, b3.x,  w1p[6], cB0);
        FMA_F32X2(cB1, b3.y,  w1p[7], cB1);

        a0 = rA[4]; a1 = rA[5]; a2v = rA[6]; a3 = rA[7];
        b0 = rB[4]; b1v = rB[5]; b2 = rB[6]; b3 = rB[7];
        FMA_F32X2(cA0, a0.x,  w1p[8],  cA0);
        FMA_F32X2(cA1, a0.y,  w1p[9],  cA1);
        FMA_F32X2(cB0, b0.x,  w1p[8],  cB0);
        FMA_F32X2(cB1, b0.y,  w1p[9],  cB1);
        FMA_F32X2(cA0, a1.x,  w1p[10], cA0);
        FMA_F32X2(cA1, a1.y,  w1p[11], cA1);
        FMA_F32X2(cB0, b1v.x, w1p[10], cB0);
        FMA_F32X2(cB1, b1v.y, w1p[11], cB1);
        FMA_F32X2(cA0, a2v.x, w1p[12], cA0);
        FMA_F32X2(cA1, a2v.y, w1p[13], cA1);
        FMA_F32X2(cB0, b2.x,  w1p[12], cB0);
        FMA_F32X2(cB1, b2.y,  w1p[13], cB1);
        FMA_F32X2(cA0, a3.x,  w1p[14], cA0);
        FMA_F32X2(cA1, a3.y,  w1p[15], cA1);
        FMA_F32X2(cB0, b3.x,  w1p[14], cB0);
        FMA_F32X2(cB1, b3.y,  w1p[15], cB1);

        ADD_F32X2(cA0, cA0, cA1);
        ADD_F32X2(cB0, cB0, cB1);
        float lo, hi;
        UNPACK_F32X2(lo, hi, cA0);
        float hA = fmaxf(lo + hi, 0.0f);
        UNPACK_F32X2(lo, hi, cB0);
        float hB = fmaxf(lo + hi, 0.0f);

        unsigned long long hd;
        ulonglong2 sA = sh2[r0];
        ulonglong2 sB = sh2[r0 + 1];
        PACK_F32X2(hd, hA, hA);
        FMA_F32X2(acc01, hd, sA.x, acc01);
        FMA_F32X2(acc23, hd, sA.y, acc23);
        PACK_F32X2(hd, hB, hB);
        FMA_F32X2(acc01, hd, sB.x, acc01);
        FMA_F32X2(acc23, hd, sB.y, acc23);
    }

    {
        float o0, o1, o2, o3;
        UNPACK_F32X2(o0, o1, acc01);
        UNPACK_F32X2(o2, o3, acc23);
        Gp[wid][lane*4+0] = o0;
        Gp[wid][lane*4+1] = o1;
        Gp[wid][lane*4+2] = o2;
        Gp[wid][lane*4+3] = o3;
    }

    // bias feature: G[32][c] = sum_m sh'[m][c]
    if (t < 32) {
        int c = t & 3, mq = t >> 2;
        float s = 0.f;
        #pragma unroll 8
        for (int m = mq; m < 128; m += 8) s += shp[m * 4 + c];
        Gp[mq][128 + c] = s;
    }
    __syncthreads();

    if (t < 132) {
        float s = 0.f;
        #pragma unroll
        for (int g = 0; g < 8; g++) s += Gp[g][t];
        g_G2[blk][t] = s;
    }
}

// ---------------------------------------------------------------------------
// Kernel B (R6 best, verbatim): 2 nodes/block, 256 blocks.
// ---------------------------------------------------------------------------
#define OFF_STAGE   0
#define OFF_GS      16384
#define OFF_SIN     (OFF_GS + 264)
#define OFF_VIN     (OFF_SIN + 32)
#define OFF_WLS     (OFF_VIN + 96)
#define OFF_WLV     (OFF_WLS + 256)
#define OFF_WOS     (OFF_WLV + 256)
#define OFF_WOV     (OFF_WOS + 256)
#define OFF_OUTS    (OFF_WOV + 256)
#define OFF_OUTV    (OFF_OUTS + 32)
#define OFF_RED     (OFF_OUTV + 96)
#define OFF_DSUM    (OFF_RED + 8)
#define SMEM_FLOATS (OFF_DSUM + 1)
#define SMEM_BYTES  (SMEM_FLOATS * 4)

__device__ __forceinline__ void chunk_compute_p(
    const float* __restrict__ stage_buf, int nrows,
    const float* __restrict__ Gs, int fbase,
    const float* si, const float* x0a, const float* x1a, const float* x2a,
    unsigned long long accS[2][2], unsigned long long accV[2][6],
    int oq, int g)
{
    int f_local = g >> 4;
    int i = g & 15;
    if (f_local >= nrows) return;
    const ulonglong2* W = (const ulonglong2*)(stage_buf + f_local * 1024 + i * 16 + oq * 4);
    ulonglong2 wss = W[0];
    ulonglong2 wvv = W[64];
    ulonglong2 wsv = W[128];
    ulonglong2 wvs = W[192];
    #pragma unroll
    for (int nl = 0; nl < 2; nl++) {
        float4 gv = *(const float4*)(Gs + nl * 132 + (fbase + f_local) * 4);
        float s  = si[nl];
        float x0 = x0a[nl], x1 = x1a[nl], x2 = x2a[nl];
        float a  = gv.x * s;
        float bc = (gv.y * x0 + gv.z * x1 + gv.w * x2) * RSQRT3;
        float c0 = gv.y * s, c1 = gv.z * s, c2 = gv.w * s;
        float d0 = gv.x * x0, d1 = gv.x * x1, d2 = gv.x * x2;
        unsigned long long a2, bc2, c02, c12, c22, d02, d12, d22;
        PACK_F32X2(a2, a, a);     PACK_F32X2(bc2, bc, bc);
        PACK_F32X2(c02, c0, c0);  PACK_F32X2(c12, c1, c1);  PACK_F32X2(c22, c2, c2);
        PACK_F32X2(d02, d0, d0);  PACK_F32X2(d12, d1, d1);  PACK_F32X2(d22, d2, d2);
        FMA_F32X2(accS[nl][0], a2,  wss.x, accS[nl][0]);
        FMA_F32X2(accS[nl][1], a2,  wss.y, accS[nl][1]);
        FMA_F32X2(accS[nl][0], bc2, wvv.x, accS[nl][0]);
        FMA_F32X2(accS[nl][1], bc2, wvv.y, accS[nl][1]);
        FMA_F32X2(accV[nl][0], c02, wsv.x, accV[nl][0]);
        FMA_F32X2(accV[nl][1], c02, wsv.y, accV[nl][1]);
        FMA_F32X2(accV[nl][0], d02, wvs.x, accV[nl][0]);
        FMA_F32X2(accV[nl][1], d02, wvs.y, accV[nl][1]);
        FMA_F32X2(accV[nl][2], c12, wsv.x, accV[nl][2]);
        FMA_F32X2(accV[nl][3], c12, wsv.y, accV[nl][3]);
        FMA_F32X2(accV[nl][2], d12, wvs.x, accV[nl][2]);
        FMA_F32X2(accV[nl][3], d12, wvs.y, accV[nl][3]);
        FMA_F32X2(accV[nl][4], c22, wsv.x, accV[nl][4]);
        FMA_F32X2(accV[nl][5], c22, wsv.y, accV[nl][5]);
        FMA_F32X2(accV[nl][4], d22, wvs.x, accV[nl][4]);
        FMA_F32X2(accV[nl][5], d22, wvs.y, accV[nl][5]);
    }
}

__device__ __forceinline__ void issue_chunk(
    unsigned stage_u32, int nc, int t,
    const float* __restrict__ fc_w2, const float* __restrict__ fc_b2)
{
    unsigned dst = stage_u32 + (unsigned)(nc & 3) * 16384u + (unsigned)t * 16u;
    if (nc < 8) {
        const float* src = fc_w2 + nc * 4096 + t * 4;
        #pragma unroll
        for (int r = 0; r < 4; r++)
            CP_ASYNC16(dst + r * 4096u, src + r * 1024);
    } else {
        CP_ASYNC16(dst, fc_b2 + t * 4);
    }
    CP_COMMIT();
}

__global__ __launch_bounds__(256, 3) void node_kernel(
    const float* __restrict__ node_attr,
    const float* __restrict__ mask,
    const float* __restrict__ w_lin_in_s,
    const float* __restrict__ w_lin_in_v,
    const float* __restrict__ fc_w2,
    const float* __restrict__ fc_b2,
    const float* __restrict__ w_lin_out_s,
    const float* __restrict__ w_lin_out_v,
    float* __restrict__ out)
{
    extern __shared__ __align__(16) float sm[];
    float* stage = sm + OFF_STAGE;
    float* part  = sm + OFF_STAGE;
    float* Gs    = sm + OFF_GS;
    float* sinS  = sm + OFF_SIN;
    float* vinS  = sm + OFF_VIN;
    float* wls   = sm + OFF_WLS;
    float* wlv   = sm + OFF_WLV;
    float* wos   = sm + OFF_WOS;
    float* wov   = sm + OFF_WOV;
    float* outsS = sm + OFF_OUTS;
    float* outvS = sm + OFF_OUTV;
    float* red   = sm + OFF_RED;

    const int t = threadIdx.x;
    const int node0 = blockIdx.x * 2;
    const int b = node0 >> 8;

    const unsigned stage_u32 = (unsigned)__cvta_generic_to_shared(stage);

    issue_chunk(stage_u32, 0, t, fc_w2, fc_b2);
    issue_chunk(stage_u32, 1, t, fc_w2, fc_b2);
    issue_chunk(stage_u32, 2, t, fc_w2, fc_b2);

    wls[t] = w_lin_in_s[t];
    wlv[t] = w_lin_in_v[t];
    wos[t] = w_lin_out_s[t];
    wov[t] = w_lin_out_v[t];
    if (t < 132) {
        #pragma unroll
        for (int nl = 0; nl < 2; nl++)
            Gs[nl*132 + t] = g_G2[(node0 + nl)*2][t] + g_G2[(node0 + nl)*2 + 1][t];
    }
    {
        float mv = mask[b * NN + t];
        #pragma unroll
        for (int o = 16; o; o >>= 1) mv += __shfl_xor_sync(0xFFFFFFFFu, mv, o);
        if ((t & 31) == 0) red[t >> 5] = mv;
    }
    __syncthreads();
    if (t == 0) {
        float s = 0.f;
        #pragma unroll
        for (int i = 0; i < 8; i++) s += red[i];
        sm[OFF_DSUM] = s - 1.0f;
    }

    if (t < 128) {
        int nl = t >> 6, u = t & 63;
        const float* na = node_attr + (size_t)(node0 + nl) * 64;
        if (u < 16) {
            float s = 0.f;
            #pragma unroll
            for (int i = 0; i < 16; i++) s += na[i] * wls[i * 16 + u];
            sinS[nl*16 + u] = s * 0.25f;
        } else {
            int idx = u - 16;
            int o = idx / 3, x = idx % 3;
            float s = 0.f;
            #pragma unroll
            for (int i = 0; i < 16; i++) s += na[16 + i * 3 + x] * wlv[i * 16 + o];
            vinS[nl*48 + o * 3 + x] = s * 0.25f;
        }
    }
    __syncthreads();

    const int oq = t & 3;
    const int g  = t >> 2;

    float si[2], x0a[2], x1a[2], x2a[2];
    {
        int i = g & 15;
        #pragma unroll
        for (int nl = 0; nl < 2; nl++) {
            si[nl]  = sinS[nl*16 + i];
            x0a[nl] = vinS[nl*48 + i*3 + 0];
            x1a[nl] = vinS[nl*48 + i*3 + 1];
            x2a[nl] = vinS[nl*48 + i*3 + 2];
        }
    }

    unsigned long long accS[2][2];
    unsigned long long accV[2][6];
    #pragma unroll
    for (int nl = 0; nl < 2; nl++) {
        accS[nl][0] = accS[nl][1] = 0ULL;
        #pragma unroll
        for (int q = 0; q < 6; q++) accV[nl][q] = 0ULL;
    }

    #pragma unroll
    for (int c = 0; c < 9; c++) {
        if (c < 7) { CP_WAIT2(); } else if (c == 7) { CP_WAIT1(); } else { CP_WAIT0(); }
        __syncthreads();
        if (c + 3 <= 8) issue_chunk(stage_u32, c + 3, t, fc_w2, fc_b2);
        chunk_compute_p(stage + (c & 3) * 4096, (c < 8) ? 4 : 1, Gs, c * 4,
                        si, x0a, x1a, x2a, accS, accV, oq, g);
    }

    __syncthreads();

    #pragma unroll
    for (int nl = 0; nl < 2; nl++) {
        #pragma unroll
        for (int h = 0; h < 2; h++) {
            float v0, v1;
            UNPACK_F32X2(v0, v1, accS[nl][h]);
            part[(nl*16 + oq*4 + h*2 + 0) * 68 + g] = v0;
            part[(nl*16 + oq*4 + h*2 + 1) * 68 + g] = v1;
        }
        #pragma unroll
        for (int x = 0; x < 3; x++)
            #pragma unroll
            for (int h = 0; h < 2; h++) {
                float v0, v1;
                UNPACK_F32X2(v0, v1, accV[nl][x*2 + h]);
                int o = oq*4 + h*2;
                part[(32 + nl*48 + o*3 + x) * 68 + g] = v0;
                part[(32 + nl*48 + (o+1)*3 + x) * 68 + g] = v1;
            }
    }
    __syncthreads();

    if (t < 128) {
        float scale = INV_FAN / sm[OFF_DSUM];
        const float4* row = (const float4*)(part + t * 68);
        float s = 0.f;
        #pragma unroll
        for (int j = 0; j < 16; j++) {
            float4 v = row[j];
            s += (v.x + v.y) + (v.z + v.w);
        }
        if (t < 32) outsS[t] = s * scale;
        else        outvS[t - 32] = s * scale;
    }
    __syncthreads();

    if (t < 128) {
        int nl = t >> 6, u = t & 63;
        const float* na = node_attr + (size_t)(node0 + nl) * 64;
        float r;
        if (u < 16) {
            float s = 0.f;
            #pragma unroll
            for (int o = 0; o < 16; o++) s += outsS[nl*16 + o] * wos[o * 16 + u];
            r = s * 0.25f + na[u];
        } else {
            int idx = u - 16;
            int o2 = idx / 3, x = idx % 3;
            float s = 0.f;
            #pragma unroll
            for (int o = 0; o < 16; o++) s += outvS[nl*48 + o * 3 + x] * wov[o * 16 + o2];
            r = s * 0.25f + na[u];
        }
        out[(size_t)(node0 + nl) * 64 + u] = r;
    }
}

extern "C" void kernel_launch(void* const* d_in, const int* in_sizes, int n_in,
                              void* d_out, int out_size) {
    const float* node_attr    = (const float*)d_in[0];
    const float* edge_attr    = (const float*)d_in[1];
    const float* edge_sh      = (const float*)d_in[2];
    const float* mask         = (const float*)d_in[3];
    const float* w_lin_in_s   = (const float*)d_in[4];
    const float* w_lin_in_v   = (const float*)d_in[5];
    const float* fc_w1        = (const float*)d_in[6];
    const float* fc_b1        = (const float*)d_in[7];
    const float* fc_w2        = (const float*)d_in[8];
    const float* fc_b2        = (const float*)d_in[9];
    const float* w_lin_out_s  = (const float*)d_in[10];
    const float* w_lin_out_v  = (const float*)d_in[11];
    float* out = (float*)d_out;

    cudaFuncSetAttribute(node_kernel,
                         cudaFuncAttributeMaxDynamicSharedMemorySize, SMEM_BYTES);

    edge_kernel<<<2 * NNODE, 256>>>(edge_attr, edge_sh, mask, fc_w1, fc_b1);
    node_kernel<<<NNODE / 2, 256, SMEM_BYTES>>>(node_attr, mask,
                                    w_lin_in_s, w_lin_in_v,
                                    fc_w2, fc_b2, w_lin_out_s, w_lin_out_v, out);
}

// round 16
// speedup vs baseline: 1.0597x; 1.0597x over previous
#include <cuda_runtime.h>

#define NN 256
#define BB 2
#define NNODE (BB*NN)

#define RSQRT3 0.5773502691896258f
#define INV_FAN 0.1767766952966369f   // 1/sqrt(32)

// partial G: per (node, half) -> [f*4+c], f in [0,33), f==32 = bias feature
__device__ float g_G2[2*NNODE][132];
// completion counters per node-pair group (self-resetting each launch)
__device__ int g_done[256];

#define PACK_F32X2(out, lo, hi) \
    asm("mov.b64 %0, {%1, %2};" : "=l"(out) : "f"(lo), "f"(hi))
#define UNPACK_F32X2(lo, hi, in) \
    asm("mov.b64 {%0, %1}, %2;" : "=f"(lo), "=f"(hi) : "l"(in))
#define FMA_F32X2(d, a, b, c) \
    asm("fma.rn.f32x2 %0, %1, %2, %3;" : "=l"(d) : "l"(a), "l"(b), "l"(c))
#define ADD_F32X2(d, a, b) \
    asm("add.rn.f32x2 %0, %1, %2;" : "=l"(d) : "l"(a), "l"(b))

#define CP_ASYNC16(dst_u32, src_ptr) \
    asm volatile("cp.async.ca.shared.global [%0], [%1], 16;" :: "r"(dst_u32), "l"(src_ptr))
#define CP_COMMIT() asm volatile("cp.async.commit_group;" ::: "memory")
#define CP_WAIT2()  asm volatile("cp.async.wait_group 2;" ::: "memory")
#define CP_WAIT1()  asm volatile("cp.async.wait_group 1;" ::: "memory")
#define CP_WAIT0()  asm volatile("cp.async.wait_group 0;" ::: "memory")

// ---------------- edge-path smem layout (floats) ----------------
#define EOFF_EA   0         // 2 x 2048
#define EOFF_SH   4096      // 128 x 4
#define EOFF_W1   4608      // 1024
#define EOFF_B1   5632      // 32
#define EOFF_GP   5664      // 8 x 132

// ---------------- node-path smem layout (floats, R6) ----------------
#define OFF_STAGE   0
#define OFF_GS      16384
#define OFF_SIN     (OFF_GS + 264)
#define OFF_VIN     (OFF_SIN + 32)
#define OFF_WLS     (OFF_VIN + 96)
#define OFF_WLV     (OFF_WLS + 256)
#define OFF_WOS     (OFF_WLV + 256)
#define OFF_WOV     (OFF_WOS + 256)
#define OFF_OUTS    (OFF_WOV + 256)
#define OFF_OUTV    (OFF_OUTS + 32)
#define OFF_RED     (OFF_OUTV + 96)
#define OFF_DSUM    (OFF_RED + 8)
#define SMEM_FLOATS (OFF_DSUM + 1)
#define SMEM_BYTES  (SMEM_FLOATS * 4)

// ---------------------------------------------------------------------------
// Edge path (R6 winner verbatim, smem via pointer): block per (node, half).
// ---------------------------------------------------------------------------
__device__ __forceinline__ void edge_path(
    float* __restrict__ sm, int blk,
    const float* __restrict__ edge_attr,
    const float* __restrict__ edge_sh,
    const float* __restrict__ mask,
    const float* __restrict__ fc_w1,
    const float* __restrict__ fc_b1)
{
    float* ea  = sm + EOFF_EA;
    float* sh  = sm + EOFF_SH;
    float* w1s = sm + EOFF_W1;
    float* b1s = sm + EOFF_B1;
    float* Gp  = sm + EOFF_GP;    // [8][132]

    const int node = blk >> 1;
    const int half = blk & 1;
    const int b = node >> 8;
    const int n = node & 255;
    const int m0 = half * 128;
    const int t = threadIdx.x;

    const float* ea_g = edge_attr + (size_t)node * NN * 32 + (size_t)m0 * 32;
    const unsigned ea_u = (unsigned)__cvta_generic_to_shared(ea);

    CP_ASYNC16(ea_u + (unsigned)t * 16u, ea_g + t * 4);
    CP_ASYNC16(ea_u + 4096u + (unsigned)t * 16u, ea_g + 1024 + t * 4);
    CP_COMMIT();
    CP_ASYNC16(ea_u + 8192u + (unsigned)t * 16u, ea_g + 2048 + t * 4);
    CP_ASYNC16(ea_u + 12288u + (unsigned)t * 16u, ea_g + 3072 + t * 4);
    CP_COMMIT();

    for (int i = t; i < 1024; i += 256) w1s[i] = fc_w1[i];
    if (t < 32) b1s[t] = fc_b1[t];
    if (t < 128) {
        int m = m0 + t;
        float mf = mask[b * NN + m] * (m != n ? 1.0f : 0.0f);
        float4 s = ((const float4*)(edge_sh + (size_t)node * NN * 4))[m];
        s.x *= mf; s.y *= mf; s.z *= mf; s.w *= mf;
        ((float4*)sh)[t] = s;
    }
    __syncthreads();

    const int f  = t & 31;
    const int mg = t >> 5;

    unsigned long long w1p[16];
    #pragma unroll
    for (int j = 0; j < 16; j++)
        PACK_F32X2(w1p[j], w1s[(2*j) * 32 + f], w1s[(2*j+1) * 32 + f]);
    unsigned long long bias2;
    PACK_F32X2(bias2, b1s[f], 0.0f);

    unsigned long long acc01 = 0ULL, acc23 = 0ULL;
    const ulonglong2* sh2 = (const ulonglong2*)sh;

    #pragma unroll
    for (int ch = 0; ch < 2; ch++) {
        if (ch == 0) { CP_WAIT1(); } else { CP_WAIT0(); }
        __syncthreads();
        const float* buf = ea + ch * 2048;
        #pragma unroll
        for (int it = 0; it < 8; it++) {
            int r = mg + it * 8;
            const ulonglong2* row = (const ulonglong2*)(buf + r * 32);
            unsigned long long c0 = bias2, c1 = 0ULL;
            ulonglong2 u0 = row[0];
            ulonglong2 u1 = row[1];
            ulonglong2 u2 = row[2];
            ulonglong2 u3 = row[3];
            FMA_F32X2(c0, u0.x, w1p[0], c0);
            FMA_F32X2(c1, u0.y, w1p[1], c1);
            FMA_F32X2(c0, u1.x, w1p[2], c0);
            FMA_F32X2(c1, u1.y, w1p[3], c1);
            u0 = row[4];
            u1 = row[5];
            FMA_F32X2(c0, u2.x, w1p[4], c0);
            FMA_F32X2(c1, u2.y, w1p[5], c1);
            FMA_F32X2(c0, u3.x, w1p[6], c0);
            FMA_F32X2(c1, u3.y, w1p[7], c1);
            u2 = row[6];
            u3 = row[7];
            FMA_F32X2(c0, u0.x, w1p[8],  c0);
            FMA_F32X2(c1, u0.y, w1p[9],  c1);
            FMA_F32X2(c0, u1.x, w1p[10], c0);
            FMA_F32X2(c1, u1.y, w1p[11], c1);
            FMA_F32X2(c0, u2.x, w1p[12], c0);
            FMA_F32X2(c1, u2.y, w1p[13], c1);
            FMA_F32X2(c0, u3.x, w1p[14], c0);
            FMA_F32X2(c1, u3.y, w1p[15], c1);
            ADD_F32X2(c0, c0, c1);
            float lo, hi;
            UNPACK_F32X2(lo, hi, c0);
            float h = fmaxf(lo + hi, 0.0f);
            unsigned long long h2;
            PACK_F32X2(h2, h, h);
            ulonglong2 s2 = sh2[ch * 64 + r];
            FMA_F32X2(acc01, h2, s2.x, acc01);
            FMA_F32X2(acc23, h2, s2.y, acc23);
        }
    }

    float o0, o1, o2, o3;
    UNPACK_F32X2(o0, o1, acc01);
    UNPACK_F32X2(o2, o3, acc23);
    Gp[mg*132 + f*4+0] = o0;
    Gp[mg*132 + f*4+1] = o1;
    Gp[mg*132 + f*4+2] = o2;
    Gp[mg*132 + f*4+3] = o3;

    if (t < 32) {
        int c = t & 3, mq = t >> 2;
        float s = 0.f;
        #pragma unroll 8
        for (int m = mq; m < 128; m += 8) s += sh[m * 4 + c];
        Gp[mq*132 + 128 + c] = s;
    }
    __syncthreads();

    if (t < 132) {
        float s = 0.f;
        #pragma unroll
        for (int g = 0; g < 8; g++) s += Gp[g*132 + t];
        g_G2[blk][t] = s;
    }
    __syncthreads();
    if (t == 0) {
        __threadfence();
        atomicAdd(&g_done[blk >> 2], 1);
    }
}

// ---------------------------------------------------------------------------
// Node path (R6 winner verbatim, + spin-wait on its 4 edge blocks).
// ---------------------------------------------------------------------------
__device__ __forceinline__ void chunk_compute_p(
    const float* __restrict__ stage_buf, int nrows,
    const float* __restrict__ Gs, int fbase,
    const float* si, const float* x0a, const float* x1a, const float* x2a,
    unsigned long long accS[2][2], unsigned long long accV[2][6],
    int oq, int g)
{
    int f_local = g >> 4;
    int i = g & 15;
    if (f_local >= nrows) return;
    const ulonglong2* W = (const ulonglong2*)(stage_buf + f_local * 1024 + i * 16 + oq * 4);
    ulonglong2 wss = W[0];
    ulonglong2 wvv = W[64];
    ulonglong2 wsv = W[128];
    ulonglong2 wvs = W[192];
    #pragma unroll
    for (int nl = 0; nl < 2; nl++) {
        float4 gv = *(const float4*)(Gs + nl * 132 + (fbase + f_local) * 4);
        float s  = si[nl];
        float x0 = x0a[nl], x1 = x1a[nl], x2 = x2a[nl];
        float a  = gv.x * s;
        float bc = (gv.y * x0 + gv.z * x1 + gv.w * x2) * RSQRT3;
        float c0 = gv.y * s, c1 = gv.z * s, c2 = gv.w * s;
        float d0 = gv.x * x0, d1 = gv.x * x1, d2 = gv.x * x2;
        unsigned long long a2, bc2, c02, c12, c22, d02, d12, d22;
        PACK_F32X2(a2, a, a);     PACK_F32X2(bc2, bc, bc);
        PACK_F32X2(c02, c0, c0);  PACK_F32X2(c12, c1, c1);  PACK_F32X2(c22, c2, c2);
        PACK_F32X2(d02, d0, d0);  PACK_F32X2(d12, d1, d1);  PACK_F32X2(d22, d2, d2);
        FMA_F32X2(accS[nl][0], a2,  wss.x, accS[nl][0]);
        FMA_F32X2(accS[nl][1], a2,  wss.y, accS[nl][1]);
        FMA_F32X2(accS[nl][0], bc2, wvv.x, accS[nl][0]);
        FMA_F32X2(accS[nl][1], bc2, wvv.y, accS[nl][1]);
        FMA_F32X2(accV[nl][0], c02, wsv.x, accV[nl][0]);
        FMA_F32X2(accV[nl][1], c02, wsv.y, accV[nl][1]);
        FMA_F32X2(accV[nl][0], d02, wvs.x, accV[nl][0]);
        FMA_F32X2(accV[nl][1], d02, wvs.y, accV[nl][1]);
        FMA_F32X2(accV[nl][2], c12, wsv.x, accV[nl][2]);
        FMA_F32X2(accV[nl][3], c12, wsv.y, accV[nl][3]);
        FMA_F32X2(accV[nl][2], d12, wvs.x, accV[nl][2]);
        FMA_F32X2(accV[nl][3], d12, wvs.y, accV[nl][3]);
        FMA_F32X2(accV[nl][4], c22, wsv.x, accV[nl][4]);
        FMA_F32X2(accV[nl][5], c22, wsv.y, accV[nl][5]);
        FMA_F32X2(accV[nl][4], d22, wvs.x, accV[nl][4]);
        FMA_F32X2(accV[nl][5], d22, wvs.y, accV[nl][5]);
    }
}

__device__ __forceinline__ void issue_chunk(
    unsigned stage_u32, int nc, int t,
    const float* __restrict__ fc_w2, const float* __restrict__ fc_b2)
{
    unsigned dst = stage_u32 + (unsigned)(nc & 3) * 16384u + (unsigned)t * 16u;
    if (nc < 8) {
        const float* src = fc_w2 + nc * 4096 + t * 4;
        #pragma unroll
        for (int r = 0; r < 4; r++)
            CP_ASYNC16(dst + r * 4096u, src + r * 1024);
    } else {
        CP_ASYNC16(dst, fc_b2 + t * 4);
    }
    CP_COMMIT();
}

__device__ __forceinline__ void node_path(
    float* __restrict__ sm, int nb,
    const float* __restrict__ node_attr,
    const float* __restrict__ mask,
    const float* __restrict__ w_lin_in_s,
    const float* __restrict__ w_lin_in_v,
    const float* __restrict__ fc_w2,
    const float* __restrict__ fc_b2,
    const float* __restrict__ w_lin_out_s,
    const float* __restrict__ w_lin_out_v,
    float* __restrict__ out)
{
    float* stage = sm + OFF_STAGE;
    float* part  = sm + OFF_STAGE;
    float* Gs    = sm + OFF_GS;
    float* sinS  = sm + OFF_SIN;
    float* vinS  = sm + OFF_VIN;
    float* wls   = sm + OFF_WLS;
    float* wlv   = sm + OFF_WLV;
    float* wos   = sm + OFF_WOS;
    float* wov   = sm + OFF_WOV;
    float* outsS = sm + OFF_OUTS;
    float* outvS = sm + OFF_OUTV;
    float* red   = sm + OFF_RED;

    const int t = threadIdx.x;
    const int node0 = nb * 2;
    const int b = node0 >> 8;

    const unsigned stage_u32 = (unsigned)__cvta_generic_to_shared(stage);

    // W2 prefetch has NO dependency on edge work — issue before waiting.
    issue_chunk(stage_u32, 0, t, fc_w2, fc_b2);
    issue_chunk(stage_u32, 1, t, fc_w2, fc_b2);
    issue_chunk(stage_u32, 2, t, fc_w2, fc_b2);

    wls[t] = w_lin_in_s[t];
    wlv[t] = w_lin_in_v[t];
    wos[t] = w_lin_out_s[t];
    wov[t] = w_lin_out_v[t];
    {
        float mv = mask[b * NN + t];
        #pragma unroll
        for (int o = 16; o; o >>= 1) mv += __shfl_xor_sync(0xFFFFFFFFu, mv, o);
        if ((t & 31) == 0) red[t >> 5] = mv;
    }

    // wait for this pair's 4 edge blocks
    if (t == 0) {
        volatile int* flag = &g_done[nb];
        while (*flag < 4) __nanosleep(64);
        __threadfence();
    }
    __syncthreads();

    if (t == 0) {
        float s = 0.f;
        #pragma unroll
        for (int i = 0; i < 8; i++) s += red[i];
        sm[OFF_DSUM] = s - 1.0f;
    }
    if (t < 132) {
        #pragma unroll
        for (int nl = 0; nl < 2; nl++)
            Gs[nl*132 + t] = g_G2[(node0 + nl)*2][t] + g_G2[(node0 + nl)*2 + 1][t];
    }
    if (t < 128) {
        int nl = t >> 6, u = t & 63;
        const float* na = node_attr + (size_t)(node0 + nl) * 64;
        if (u < 16) {
            float s = 0.f;
            #pragma unroll
            for (int i = 0; i < 16; i++) s += na[i] * wls[i * 16 + u];
            sinS[nl*16 + u] = s * 0.25f;
        } else {
            int idx = u - 16;
            int o = idx / 3, x = idx % 3;
            float s = 0.f;
            #pragma unroll
            for (int i = 0; i < 16; i++) s += na[16 + i * 3 + x] * wlv[i * 16 + o];
            vinS[nl*48 + o * 3 + x] = s * 0.25f;
        }
    }
    __syncthreads();
    if (t == 0) g_done[nb] = 0;   // self-reset for next launch (after G consumed)

    const int oq = t & 3;
    const int g  = t >> 2;

    float si[2], x0a[2], x1a[2], x2a[2];
    {
        int i = g & 15;
        #pragma unroll
        for (int nl = 0; nl < 2; nl++) {
            si[nl]  = sinS[nl*16 + i];
            x0a[nl] = vinS[nl*48 + i*3 + 0];
            x1a[nl] = vinS[nl*48 + i*3 + 1];
            x2a[nl] = vinS[nl*48 + i*3 + 2];
        }
    }

    unsigned long long accS[2][2];
    unsigned long long accV[2][6];
    #pragma unroll
    for (int nl = 0; nl < 2; nl++) {
        accS[nl][0] = accS[nl][1] = 0ULL;
        #pragma unroll
        for (int q = 0; q < 6; q++) accV[nl][q] = 0ULL;
    }

    #pragma unroll
    for (int c = 0; c < 9; c++) {
        if (c < 7) { CP_WAIT2(); } else if (c == 7) { CP_WAIT1(); } else { CP_WAIT0(); }
        __syncthreads();
        if (c + 3 <= 8) issue_chunk(stage_u32, c + 3, t, fc_w2, fc_b2);
        chunk_compute_p(stage + (c & 3) * 4096, (c < 8) ? 4 : 1, Gs, c * 4,
                        si, x0a, x1a, x2a, accS, accV, oq, g);
    }

    __syncthreads();

    #pragma unroll
    for (int nl = 0; nl < 2; nl++) {
        #pragma unroll
        for (int h = 0; h < 2; h++) {
            float v0, v1;
            UNPACK_F32X2(v0, v1, accS[nl][h]);
            part[(nl*16 + oq*4 + h*2 + 0) * 68 + g] = v0;
            part[(nl*16 + oq*4 + h*2 + 1) * 68 + g] = v1;
        }
        #pragma unroll
        for (int x = 0; x < 3; x++)
            #pragma unroll
            for (int h = 0; h < 2; h++) {
                float v0, v1;
                UNPACK_F32X2(v0, v1, accV[nl][x*2 + h]);
                int o = oq*4 + h*2;
                part[(32 + nl*48 + o*3 + x) * 68 + g] = v0;
                part[(32 + nl*48 + (o+1)*3 + x) * 68 + g] = v1;
            }
    }
    __syncthreads();

    if (t < 128) {
        float scale = INV_FAN / sm[OFF_DSUM];
        const float4* row = (const float4*)(part + t * 68);
        float s = 0.f;
        #pragma unroll
        for (int j = 0; j < 16; j++) {
            float4 v = row[j];
            s += (v.x + v.y) + (v.z + v.w);
        }
        if (t < 32) outsS[t] = s * scale;
        else        outvS[t - 32] = s * scale;
    }
    __syncthreads();

    if (t < 128) {
        int nl = t >> 6, u = t & 63;
        const float* na = node_attr + (size_t)(node0 + nl) * 64;
        float r;
        if (u < 16) {
            float s = 0.f;
            #pragma unroll
            for (int o = 0; o < 16; o++) s += outsS[nl*16 + o] * wos[o * 16 + u];
            r = s * 0.25f + na[u];
        } else {
            int idx = u - 16;
            int o2 = idx / 3, x = idx % 3;
            float s = 0.f;
            #pragma unroll
            for (int o = 0; o < 16; o++) s += outvS[nl*48 + o * 3 + x] * wov[o * 16 + o2];
            r = s * 0.25f + na[u];
        }
        out[(size_t)(node0 + nl) * 64 + u] = r;
    }
}

// ---------------------------------------------------------------------------
// Fused launcher kernel
// ---------------------------------------------------------------------------
__global__ __launch_bounds__(256) void fused_kernel(
    const float* __restrict__ node_attr,
    const float* __restrict__ edge_attr,
    const float* __restrict__ edge_sh,
    const float* __restrict__ mask,
    const float* __restrict__ w_lin_in_s,
    const float* __restrict__ w_lin_in_v,
    const float* __restrict__ fc_w1,
    const float* __restrict__ fc_b1,
    const float* __restrict__ fc_w2,
    const float* __restrict__ fc_b2,
    const float* __restrict__ w_lin_out_s,
    const float* __restrict__ w_lin_out_v,
    float* __restrict__ out)
{
    extern __shared__ __align__(16) float sm[];
    if (blockIdx.x < 2 * NNODE) {
        edge_path(sm, blockIdx.x, edge_attr, edge_sh, mask, fc_w1, fc_b1);
    } else {
        node_path(sm, blockIdx.x - 2 * NNODE, node_attr, mask,
                  w_lin_in_s, w_lin_in_v, fc_w2, fc_b2,
                  w_lin_out_s, w_lin_out_v, out);
    }
}

extern "C" void kernel_launch(void* const* d_in, const int* in_sizes, int n_in,
                              void* d_out, int out_size) {
    const float* node_attr    = (const float*)d_in[0];
    const float* edge_attr    = (const float*)d_in[1];
    const float* edge_sh      = (const float*)d_in[2];
    const float* mask         = (const float*)d_in[3];
    const float* w_lin_in_s   = (const float*)d_in[4];
    const float* w_lin_in_v   = (const float*)d_in[5];
    const float* fc_w1        = (const float*)d_in[6];
    const float* fc_b1        = (const float*)d_in[7];
    const float* fc_w2        = (const float*)d_in[8];
    const float* fc_b2        = (const float*)d_in[9];
    const float* w_lin_out_s  = (const float*)d_in[10];
    const float* w_lin_out_v  = (const float*)d_in[11];
    float* out = (float*)d_out;

    cudaFuncSetAttribute(fused_kernel,
                         cudaFuncAttributeMaxDynamicSharedMemorySize, SMEM_BYTES);

    fused_kernel<<<2 * NNODE + NNODE / 2, 256, SMEM_BYTES>>>(
        node_attr, edge_attr, edge_sh, mask,
        w_lin_in_s, w_lin_in_v, fc_w1, fc_b1, fc_w2, fc_b2,
        w_lin_out_s, w_lin_out_v, out);
}